// round 2
// baseline (speedup 1.0000x reference)
#include <cuda_runtime.h>
#include <cuda_bf16.h>
#include <math.h>

// Problem shape (fixed by the reference):
//   q,k,v: [H, N, D] fp32   adj: [H, N, N] fp32   alpha,beta: [H] fp32
//   out:   [H, N, D] fp32
#define HH 8
#define NN 4096
#define DD 64

// ---------------------------------------------------------------------------
// Math identity used by this kernel pair:
//   P = softmax(Q K^T * scale + adj)                (full softmax, incl. diag)
//   out[h,n,:] = beta[h] * (P[h,n,:] @ V[h])
//              + (alpha[h] - beta[h]*P[h,n,n]) * v[h,n,:]
// Kernel 1 writes the alpha*v term for every element.
// Kernel 2 adds the beta-scaled attention correction. When beta[h] == 0 the
// correction is identically zero (exact algebra, not an approximation), so
// the block early-exits after reading beta[h]. The kernel is fully general:
// any head with beta != 0 takes the full fused softmax path.
// ---------------------------------------------------------------------------

// Kernel 1: out = alpha[h] * v   (float4 vectorized; D=64 -> 16 float4/row,
// rows never straddle a float4, so h = i / (N*D/4) is exact)
__global__ void diag_alpha_v_kernel(const float* __restrict__ v,
                                    const float* __restrict__ alpha,
                                    float* __restrict__ out) {
    long i = (long)blockIdx.x * blockDim.x + threadIdx.x;     // float4 index
    const long total4 = (long)HH * NN * (DD / 4);             // 524288
    if (i >= total4) return;
    int h = (int)(i / ((long)NN * (DD / 4)));                 // i / 65536
    float a = __ldg(&alpha[h]);
    float4 val = ((const float4*)v)[i];
    val.x *= a; val.y *= a; val.z *= a; val.w *= a;
    ((float4*)out)[i] = val;
}

// Kernel 2: out += beta[h] * (P @ V - P[n,n] * v_n)
// grid = (N/ROWS_PER_BLOCK, H), 256 threads.
#define ROWS_PER_BLOCK 16
__global__ void attn_correction_kernel(const float* __restrict__ q,
                                       const float* __restrict__ k,
                                       const float* __restrict__ v,
                                       const float* __restrict__ adj,
                                       const float* __restrict__ beta,
                                       float* __restrict__ out) {
    const int h = blockIdx.y;
    const float b = __ldg(&beta[h]);
    if (b == 0.0f) return;   // exact: beta * (finite) == 0, nothing to add

    __shared__ float s[NN];      // 16 KB: scores -> exp weights for one row
    __shared__ float qs[DD];
    __shared__ float red[256];

    const int tid = threadIdx.x;
    const float scale = rsqrtf((float)DD);
    const float* kh = k + (long)h * NN * DD;
    const float* vh = v + (long)h * NN * DD;

    for (int rr = 0; rr < ROWS_PER_BLOCK; rr++) {
        const int r = blockIdx.x * ROWS_PER_BLOCK + rr;
        if (tid < DD) qs[tid] = q[((long)h * NN + r) * DD + tid];
        __syncthreads();

        const float* adjr = adj + ((long)h * NN + r) * NN;

        // scores + running max
        float lmax = -INFINITY;
        for (int m = tid; m < NN; m += 256) {
            const float* km = kh + (long)m * DD;
            float dot = 0.f;
            #pragma unroll 16
            for (int d = 0; d < DD; d++) dot = fmaf(qs[d], km[d], dot);
            float val = dot * scale + adjr[m];
            s[m] = val;
            lmax = fmaxf(lmax, val);
        }
        red[tid] = lmax; __syncthreads();
        for (int o = 128; o > 0; o >>= 1) {
            if (tid < o) red[tid] = fmaxf(red[tid], red[tid + o]);
            __syncthreads();
        }
        const float mx = red[0]; __syncthreads();

        // exp + sum
        float lsum = 0.f;
        for (int m = tid; m < NN; m += 256) {
            float e = expf(s[m] - mx);
            s[m] = e;
            lsum += e;
        }
        red[tid] = lsum; __syncthreads();
        for (int o = 128; o > 0; o >>= 1) {
            if (tid < o) red[tid] += red[tid + o];
            __syncthreads();
        }
        const float inv = 1.0f / red[0]; __syncthreads();
        const float prr = s[r] * inv;    // P[r,r]

        // weighted V accumulate: thread t -> dim d = t&63, group g = t>>6
        const int d = tid & 63, g = tid >> 6;
        float acc = 0.f;
        for (int m = g; m < NN; m += 4) acc += s[m] * vh[(long)m * DD + d];
        red[tid] = acc; __syncthreads();
        if (g == 0) {
            float tot = red[d] + red[64 + d] + red[128 + d] + red[192 + d];
            float corr = b * (tot * inv - prr * vh[(long)r * DD + d]);
            out[((long)h * NN + r) * DD + d] += corr;
        }
        __syncthreads();
    }
}

extern "C" void kernel_launch(void* const* d_in, const int* in_sizes, int n_in,
                              void* d_out, int out_size) {
    const float* q     = (const float*)d_in[0];
    const float* k     = (const float*)d_in[1];
    const float* v     = (const float*)d_in[2];
    const float* adj   = (const float*)d_in[3];
    const float* alpha = (const float*)d_in[4];
    const float* beta  = (const float*)d_in[5];
    float* out = (float*)d_out;

    // out = alpha[h] * v   (writes every output element)
    const long total4 = (long)HH * NN * (DD / 4);
    diag_alpha_v_kernel<<<(unsigned)((total4 + 255) / 256), 256>>>(v, alpha, out);

    // out += beta[h] * (softmax-attention correction); early-exits per head
    // when beta[h] == 0 (exact).
    dim3 grid(NN / ROWS_PER_BLOCK, HH);
    attn_correction_kernel<<<grid, 256>>>(q, k, v, adj, beta, out);
}

// round 4
// speedup vs baseline: 1.2605x; 1.2605x over previous
#include <cuda_runtime.h>
#include <cuda_bf16.h>
#include <math.h>

// Problem shape (fixed by the reference):
//   q,k,v: [H, N, D] fp32   adj: [H, N, N] fp32   alpha,beta: [H] fp32
//   out:   [H, N, D] fp32
#define HH 8
#define NN 4096
#define DD 64
#define ROWS 64          // rows per block
#define NTHREADS 256

// ---------------------------------------------------------------------------
// Math identity:
//   P = softmax(Q K^T * scale + adj)
//   out[h,n,:] = beta[h] * (P[h,n,:] @ V[h])
//              + (alpha[h] - beta[h]*P[h,n,n]) * v[h,n,:]
// Single fused kernel:
//   phase 1: out = alpha[h] * v for this block's 64-row slab (vectorized,
//            4 float4 per thread -> MLP=4, bandwidth-bound).
//   phase 2: only if beta[h] != 0 (exact algebraic zero otherwise), compute
//            the full-softmax correction and add it. Fully general.
// 18KB static smem does NOT cost occupancy: the 2048-thread/SM cap binds
// first (8 blocks x 18KB = 144KB < 228KB).
// ---------------------------------------------------------------------------
__global__ void __launch_bounds__(NTHREADS)
fused_adj_attention_kernel(const float* __restrict__ q,
                           const float* __restrict__ k,
                           const float* __restrict__ v,
                           const float* __restrict__ adj,
                           const float* __restrict__ alpha,
                           const float* __restrict__ beta,
                           float* __restrict__ out) {
    const int h    = blockIdx.y;
    const int row0 = blockIdx.x * ROWS;
    const int tid  = threadIdx.x;

    const float a = __ldg(&alpha[h]);
    const float b = __ldg(&beta[h]);

    // ---- phase 1: out = alpha * v for this slab (64 rows x 64 dims) ----
    {
        const float4* v4 = (const float4*)(v   + ((long)h * NN + row0) * DD);
        float4*       o4 = (float4*)      (out + ((long)h * NN + row0) * DD);
        #pragma unroll
        for (int j = 0; j < (ROWS * DD / 4) / NTHREADS; j++) {   // 4 iters
            const int idx = tid + j * NTHREADS;
            float4 t = v4[idx];
            t.x *= a; t.y *= a; t.z *= a; t.w *= a;
            o4[idx] = t;
        }
    }

    if (b == 0.0f) return;   // exact: beta * (finite correction) == 0

    // ---- phase 2: out += beta * (P @ V - P[r,r] * v_r)  (general path) ----
    __shared__ float s[NN];        // 16 KB: scores -> exp weights, one row
    __shared__ float qs[DD];
    __shared__ float red[NTHREADS];

    const float scale = rsqrtf((float)DD);
    const float* kh = k + (long)h * NN * DD;
    const float* vh = v + (long)h * NN * DD;

    __syncthreads();   // phase-1 writes to out done before += below (same block)

    for (int rr = 0; rr < ROWS; rr++) {
        const int r = row0 + rr;
        if (tid < DD) qs[tid] = q[((long)h * NN + r) * DD + tid];
        __syncthreads();

        const float* adjr = adj + ((long)h * NN + r) * NN;

        // scores + running max
        float lmax = -INFINITY;
        for (int m = tid; m < NN; m += NTHREADS) {
            const float* km = kh + (long)m * DD;
            float dot = 0.f;
            #pragma unroll 16
            for (int d = 0; d < DD; d++) dot = fmaf(qs[d], km[d], dot);
            float val = dot * scale + adjr[m];
            s[m] = val;
            lmax = fmaxf(lmax, val);
        }
        red[tid] = lmax; __syncthreads();
        for (int o = NTHREADS / 2; o > 0; o >>= 1) {
            if (tid < o) red[tid] = fmaxf(red[tid], red[tid + o]);
            __syncthreads();
        }
        const float mx = red[0]; __syncthreads();

        // exp + sum
        float lsum = 0.f;
        for (int m = tid; m < NN; m += NTHREADS) {
            float e = expf(s[m] - mx);
            s[m] = e;
            lsum += e;
        }
        red[tid] = lsum; __syncthreads();
        for (int o = NTHREADS / 2; o > 0; o >>= 1) {
            if (tid < o) red[tid] += red[tid + o];
            __syncthreads();
        }
        const float inv = 1.0f / red[0]; __syncthreads();
        const float prr = s[r] * inv;    // P[r,r]

        // weighted V accumulate: thread t -> dim d = t&63, group g = t>>6
        const int d = tid & 63, g = tid >> 6;
        float acc = 0.f;
        for (int m = g; m < NN; m += 4) acc += s[m] * vh[(long)m * DD + d];
        red[tid] = acc; __syncthreads();
        if (g == 0) {
            float tot = red[d] + red[64 + d] + red[128 + d] + red[192 + d];
            float corr = b * (tot * inv - prr * vh[(long)r * DD + d]);
            out[((long)h * NN + r) * DD + d] += corr;
        }
        __syncthreads();
    }
}

extern "C" void kernel_launch(void* const* d_in, const int* in_sizes, int n_in,
                              void* d_out, int out_size) {
    const float* q     = (const float*)d_in[0];
    const float* k     = (const float*)d_in[1];
    const float* v     = (const float*)d_in[2];
    const float* adj   = (const float*)d_in[3];
    const float* alpha = (const float*)d_in[4];
    const float* beta  = (const float*)d_in[5];
    float* out = (float*)d_out;

    dim3 grid(NN / ROWS, HH);   // (64, 8) = 512 blocks
    fused_adj_attention_kernel<<<grid, NTHREADS>>>(q, k, v, adj, alpha, beta, out);
}